// round 10
// baseline (speedup 1.0000x reference)
#include <cuda_runtime.h>

#define BB 8
#define LL 1024
#define DD 512
#define HD 4096

// Accumulators. Zero at module load (first call OK); k4's epilogue re-zeroes
// xsum2/vsum4 for the next replay; zc re-zeroed by kA's extra blocks each call.
__device__ __align__(16) float g_xsum2[2][BB * DD];   // 32 KB
__device__ __align__(16) float g_vsum4[4][BB * HD];   // 512 KB
__device__ __align__(16) float g_zc[8][BB * DD];      // 128 KB
__device__ __align__(16) float g_z[BB * DD];          // merged z, 16 KB
__device__ int g_tick3;                                // k3 last-block ticket

__device__ __forceinline__ void red_add_v4(float* a, float4 v) {
    asm volatile("red.global.add.v4.f32 [%0], {%1,%2,%3,%4};"
                 :: "l"(a), "f"(v.x), "f"(v.y), "f"(v.z), "f"(v.w) : "memory");
}

// kA: blocks [0,512): xsum += input over 16-row chunks (red into 2 copies).
//     blocks [512,544): zero g_zc for this call.
__global__ __launch_bounds__(256) void kA(const float* __restrict__ x) {
    int blk = blockIdx.x, t = threadIdx.x;
    if (blk >= 512) {
        int q = (blk - 512) * 256 + t;   // 8192 quads
        reinterpret_cast<float4*>(&g_zc[0][0])[q] = make_float4(0.f, 0.f, 0.f, 0.f);
        return;
    }
    int b = blk >> 6, c = blk & 63;          // 64 L-chunks of 16 rows
    int h = t >> 7, q = t & 127;             // 8-row half, quad
    const float4* p = reinterpret_cast<const float4*>(x)
                    + (size_t)b * LL * 128 + (size_t)(c * 16 + h * 8) * 128 + q;
    float4 s = make_float4(0.f, 0.f, 0.f, 0.f);
#pragma unroll
    for (int r = 0; r < 8; ++r) {
        float4 v = p[r * 128];
        s.x += v.x; s.y += v.y; s.z += v.z; s.w += v.w;
    }
    red_add_v4(&g_xsum2[h][b * DD + 4 * q], s);
}

// k2: vsum += xsum @ wv (+ L*bv on kc==0).  wv is [DD x HD] row-major.
// grid (jb=8, kc=32), 512 threads; 32 KB tile; in-block kg-half combine.
__global__ void k2_vsum(const float* __restrict__ wv, const float* __restrict__ bv) {
    __shared__ float4 sw[16 * 128];   // 32 KB
    __shared__ float4 sc[256 * 4];    // 16 KB; first 512 B doubles as xs
    float* xs = reinterpret_cast<float*>(sc);

    int t = threadIdx.x;
    int jb = blockIdx.x, kc = blockIdx.y;
    int k0 = kc * 16;

    const float4* w4 = reinterpret_cast<const float4*>(wv);
#pragma unroll
    for (int u = 0; u < 4; ++u) {
        int g = t + u * 512;
        int kk = g >> 7, jq = g & 127;
        sw[g] = w4[(size_t)(k0 + kk) * (HD / 4) + jb * 128 + jq];
    }
    if (t < 128) {
        int b = t >> 4, kk = t & 15;
        int a = b * DD + k0 + kk;
        xs[t] = g_xsum2[0][a] + g_xsum2[1][a];
    }
    __syncthreads();

    int jq = t & 127, kg = (t >> 7) & 1, bg = t >> 8;
    float4 acc[4];
#pragma unroll
    for (int i = 0; i < 4; ++i) acc[i] = make_float4(0.f, 0.f, 0.f, 0.f);
#pragma unroll
    for (int kk = 0; kk < 8; ++kk) {
        float4 wq = sw[(kg * 8 + kk) * 128 + jq];
#pragma unroll
        for (int bi = 0; bi < 4; ++bi) {
            float xv = xs[(bg * 4 + bi) * 16 + kg * 8 + kk];
            acc[bi].x += xv * wq.x; acc[bi].y += xv * wq.y;
            acc[bi].z += xv * wq.z; acc[bi].w += xv * wq.w;
        }
    }
    __syncthreads();
    int slot = (bg * 128 + jq) * 4;
    if (kg == 1) {
#pragma unroll
        for (int bi = 0; bi < 4; ++bi) sc[slot + bi] = acc[bi];
    }
    __syncthreads();
    if (kg == 0) {
        float4 lb = make_float4(0.f, 0.f, 0.f, 0.f);
        if (kc == 0) {
            float4 bv4 = reinterpret_cast<const float4*>(bv)[jb * 128 + jq];
            lb.x = 1024.f * bv4.x; lb.y = 1024.f * bv4.y;
            lb.z = 1024.f * bv4.z; lb.w = 1024.f * bv4.w;
        }
        float* base = &g_vsum4[kc & 3][0];
#pragma unroll
        for (int bi = 0; bi < 4; ++bi) {
            float4 o = sc[slot + bi];
            o.x += acc[bi].x + lb.x; o.y += acc[bi].y + lb.y;
            o.z += acc[bi].z + lb.z; o.w += acc[bi].w + lb.w;
            red_add_v4(base + (bg * 4 + bi) * HD + jb * 512 + 4 * jq, o);
        }
    }
}

// k3: zc += vsum @ fc_w (+ fc_b on jc==0), then the LAST block (ticket) merges
// the 8 zc copies into g_z so k4 stages z with a single load.
__global__ void k3_z(const float* __restrict__ fcw, const float* __restrict__ fcb) {
    __shared__ float4 sw[16 * 128];
    __shared__ float4 sc[256 * 4];
    __shared__ int s_last;
    float* vs = reinterpret_cast<float*>(sc);

    int t = threadIdx.x;
    int jc = blockIdx.x;
    int j0 = jc * 16;

    const float4* w4 = reinterpret_cast<const float4*>(fcw);
#pragma unroll
    for (int u = 0; u < 4; ++u) {
        int g = t + u * 512;
        int jj = g >> 7, iq = g & 127;
        sw[g] = w4[(size_t)(j0 + jj) * (DD / 4) + iq];
    }
    if (t < 128) {
        int b = t >> 4, jj = t & 15;
        int a = b * HD + j0 + jj;
        vs[t] = g_vsum4[0][a] + g_vsum4[1][a] + g_vsum4[2][a] + g_vsum4[3][a];
    }
    __syncthreads();

    int iq = t & 127, jg = (t >> 7) & 1, bg = t >> 8;
    float4 acc[4];
#pragma unroll
    for (int i = 0; i < 4; ++i) acc[i] = make_float4(0.f, 0.f, 0.f, 0.f);
#pragma unroll
    for (int jj = 0; jj < 8; ++jj) {
        float4 wq = sw[(jg * 8 + jj) * 128 + iq];
#pragma unroll
        for (int bi = 0; bi < 4; ++bi) {
            float vv = vs[(bg * 4 + bi) * 16 + jg * 8 + jj];
            acc[bi].x += vv * wq.x; acc[bi].y += vv * wq.y;
            acc[bi].z += vv * wq.z; acc[bi].w += vv * wq.w;
        }
    }
    __syncthreads();
    int slot = (bg * 128 + iq) * 4;
    if (jg == 1) {
#pragma unroll
        for (int bi = 0; bi < 4; ++bi) sc[slot + bi] = acc[bi];
    }
    __syncthreads();
    if (jg == 0) {
        float4 fb = make_float4(0.f, 0.f, 0.f, 0.f);
        if (jc == 0) fb = reinterpret_cast<const float4*>(fcb)[iq];
        float* base = &g_zc[jc & 7][0];
#pragma unroll
        for (int bi = 0; bi < 4; ++bi) {
            float4 o = sc[slot + bi];
            o.x += acc[bi].x + fb.x; o.y += acc[bi].y + fb.y;
            o.z += acc[bi].z + fb.z; o.w += acc[bi].w + fb.w;
            red_add_v4(base + (bg * 4 + bi) * DD + 4 * iq, o);
        }
    }

    // --- last-block merge: zc[8] -> g_z ---
    __threadfence();                 // every thread: make its reds visible
    __syncthreads();
    if (t == 0) {
        int old = atomicAdd(&g_tick3, 1);
        s_last = (old == 255);
    }
    __syncthreads();
    if (s_last) {
        __threadfence();             // acquire side
        // 1024 quads, 512 threads -> 2 quads each; sum 8 copies per quad.
#pragma unroll
        for (int u = 0; u < 2; ++u) {
            int q = t + u * 512;
            float4 s = make_float4(0.f, 0.f, 0.f, 0.f);
#pragma unroll
            for (int c = 0; c < 8; ++c) {
                float4 v = reinterpret_cast<const float4*>(&g_zc[c][0])[q];
                s.x += v.x; s.y += v.y; s.z += v.z; s.w += v.w;
            }
            reinterpret_cast<float4*>(g_z)[q] = s;
        }
        if (t == 0) g_tick3 = 0;     // reset for next replay
    }
}

// k4: out = LayerNorm(g_z[b] + x[b,l]) * g + beta.
// 512 blocks x 256 threads, two rows per warp; z/ln_g/ln_b staged in shared
// with ONE load each (z pre-merged by k3). Epilogue resets for next replay.
__global__ __launch_bounds__(256, 4) void k4_ln(
        const float* __restrict__ x,
        const float* __restrict__ lng, const float* __restrict__ lnb,
        float* __restrict__ out) {
    __shared__ float4 zs[128];   // merged z row for this b
    __shared__ float4 gs[128];   // ln_g
    __shared__ float4 bs[128];   // ln_b
    int t = threadIdx.x, blk = blockIdx.x;
    int b = blk >> 6;                      // 64 blocks (16 rows each) per batch

    if (t < 128) {
        zs[t] = reinterpret_cast<const float4*>(g_z)[b * 128 + t];
    } else {
        int u = t - 128;
        gs[u] = reinterpret_cast<const float4*>(lng)[u];
        bs[u] = reinterpret_cast<const float4*>(lnb)[u];
    }
    __syncthreads();

    int warp = t >> 5, lane = t & 31;
    int row0 = blk * 16 + warp * 2;

    const float4* xp0 = reinterpret_cast<const float4*>(x) + (size_t)row0 * 128;
    const float4* xp1 = xp0 + 128;

    float4 xa[4], xb[4];
#pragma unroll
    for (int i = 0; i < 4; ++i) xa[i] = xp0[lane + 32 * i];
#pragma unroll
    for (int i = 0; i < 4; ++i) xb[i] = xp1[lane + 32 * i];

    float sa = 0.f, qa = 0.f, sb = 0.f, qb = 0.f;
#pragma unroll
    for (int i = 0; i < 4; ++i) {
        float4 z = zs[lane + 32 * i];
        float y;
        y = xa[i].x + z.x; sa += y; qa += y * y;
        y = xa[i].y + z.y; sa += y; qa += y * y;
        y = xa[i].z + z.z; sa += y; qa += y * y;
        y = xa[i].w + z.w; sa += y; qa += y * y;
        y = xb[i].x + z.x; sb += y; qb += y * y;
        y = xb[i].y + z.y; sb += y; qb += y * y;
        y = xb[i].z + z.z; sb += y; qb += y * y;
        y = xb[i].w + z.w; sb += y; qb += y * y;
    }
#pragma unroll
    for (int o = 16; o > 0; o >>= 1) {
        sa += __shfl_xor_sync(0xFFFFFFFFu, sa, o);
        qa += __shfl_xor_sync(0xFFFFFFFFu, qa, o);
        sb += __shfl_xor_sync(0xFFFFFFFFu, sb, o);
        qb += __shfl_xor_sync(0xFFFFFFFFu, qb, o);
    }
    float mua  = sa * (1.0f / DD);
    float inva = rsqrtf(qa * (1.0f / DD) - mua * mua + 1e-5f);
    float mub  = sb * (1.0f / DD);
    float invb = rsqrtf(qb * (1.0f / DD) - mub * mub + 1e-5f);

    float4* op0 = reinterpret_cast<float4*>(out) + (size_t)row0 * 128;
    float4* op1 = op0 + 128;
#pragma unroll
    for (int i = 0; i < 4; ++i) {
        float4 z  = zs[lane + 32 * i];
        float4 gv = gs[lane + 32 * i];
        float4 be = bs[lane + 32 * i];
        float4 o;
        o.x = (xa[i].x + z.x - mua) * inva * gv.x + be.x;
        o.y = (xa[i].y + z.y - mua) * inva * gv.y + be.y;
        o.z = (xa[i].z + z.z - mua) * inva * gv.z + be.z;
        o.w = (xa[i].w + z.w - mua) * inva * gv.w + be.w;
        op0[lane + 32 * i] = o;
        o.x = (xb[i].x + z.x - mub) * invb * gv.x + be.x;
        o.y = (xb[i].y + z.y - mub) * invb * gv.y + be.y;
        o.z = (xb[i].z + z.z - mub) * invb * gv.z + be.z;
        o.w = (xb[i].w + z.w - mub) * invb * gv.w + be.w;
        op1[lane + 32 * i] = o;
    }

    // Epilogue resets for next replay (k4 reads neither buffer).
    float4 z4 = make_float4(0.f, 0.f, 0.f, 0.f);
    if (t < 64)
        reinterpret_cast<float4*>(&g_vsum4[0][0])[blk * 64 + t] = z4;   // 32768 quads
    if (t < 4)
        reinterpret_cast<float4*>(&g_xsum2[0][0])[blk * 4 + t] = z4;    // 2048 quads
}

extern "C" void kernel_launch(void* const* d_in, const int* in_sizes, int n_in,
                              void* d_out, int out_size) {
    const float* input = (const float*)d_in[0];
    const float* wv    = (const float*)d_in[5];
    const float* bv    = (const float*)d_in[6];
    const float* fcw   = (const float*)d_in[9];
    const float* fcb   = (const float*)d_in[10];
    const float* lng   = (const float*)d_in[11];
    const float* lnb   = (const float*)d_in[12];
    float* out = (float*)d_out;

    kA     <<<544, 256>>>(input);
    k2_vsum<<<dim3(8, 32), 512>>>(wv, bv);
    k3_z   <<<256, 512>>>(fcw, fcb);
    k4_ln  <<<512, 256>>>(input, lng, lnb, out);
}

// round 11
// speedup vs baseline: 1.1204x; 1.1204x over previous
#include <cuda_runtime.h>

#define BB 8
#define LL 1024
#define DD 512
#define HD 4096

// Accumulators. Zero at module load (first call OK); k4's epilogue re-zeroes
// xsum2/vsum4 for the next replay; zc re-zeroed by kA's extra blocks each call.
__device__ __align__(16) float g_xsum2[2][BB * DD];   // 32 KB
__device__ __align__(16) float g_vsum4[4][BB * HD];   // 512 KB
__device__ __align__(16) float g_zc[8][BB * DD];      // 128 KB

__device__ __forceinline__ void red_add_v4(float* a, float4 v) {
    asm volatile("red.global.add.v4.f32 [%0], {%1,%2,%3,%4};"
                 :: "l"(a), "f"(v.x), "f"(v.y), "f"(v.z), "f"(v.w) : "memory");
}

// kA: blocks [0,512): xsum += input over 16-row chunks (red into 2 copies).
//     blocks [512,544): zero g_zc for this call.
__global__ __launch_bounds__(256) void kA(const float* __restrict__ x) {
    int blk = blockIdx.x, t = threadIdx.x;
    if (blk >= 512) {
        int q = (blk - 512) * 256 + t;   // 8192 quads
        reinterpret_cast<float4*>(&g_zc[0][0])[q] = make_float4(0.f, 0.f, 0.f, 0.f);
        return;
    }
    int b = blk >> 6, c = blk & 63;          // 64 L-chunks of 16 rows
    int h = t >> 7, q = t & 127;             // 8-row half, quad
    const float4* p = reinterpret_cast<const float4*>(x)
                    + (size_t)b * LL * 128 + (size_t)(c * 16 + h * 8) * 128 + q;
    float4 s = make_float4(0.f, 0.f, 0.f, 0.f);
#pragma unroll
    for (int r = 0; r < 8; ++r) {
        float4 v = p[r * 128];
        s.x += v.x; s.y += v.y; s.z += v.z; s.w += v.w;
    }
    red_add_v4(&g_xsum2[h][b * DD + 4 * q], s);
}

// k2: vsum += xsum @ wv (+ L*bv on kc==0).  wv is [DD x HD] row-major.
// grid (jb=8, kc=32), 512 threads; 32 KB tile; in-block kg-half combine.
__global__ void k2_vsum(const float* __restrict__ wv, const float* __restrict__ bv) {
    __shared__ float4 sw[16 * 128];   // 32 KB
    __shared__ float4 sc[256 * 4];    // 16 KB; first 512 B doubles as xs
    float* xs = reinterpret_cast<float*>(sc);

    int t = threadIdx.x;
    int jb = blockIdx.x, kc = blockIdx.y;
    int k0 = kc * 16;

    const float4* w4 = reinterpret_cast<const float4*>(wv);
#pragma unroll
    for (int u = 0; u < 4; ++u) {
        int g = t + u * 512;
        int kk = g >> 7, jq = g & 127;
        sw[g] = w4[(size_t)(k0 + kk) * (HD / 4) + jb * 128 + jq];
    }
    if (t < 128) {
        int b = t >> 4, kk = t & 15;
        int a = b * DD + k0 + kk;
        xs[t] = g_xsum2[0][a] + g_xsum2[1][a];
    }
    __syncthreads();

    int jq = t & 127, kg = (t >> 7) & 1, bg = t >> 8;
    float4 acc[4];
#pragma unroll
    for (int i = 0; i < 4; ++i) acc[i] = make_float4(0.f, 0.f, 0.f, 0.f);
#pragma unroll
    for (int kk = 0; kk < 8; ++kk) {
        float4 wq = sw[(kg * 8 + kk) * 128 + jq];
#pragma unroll
        for (int bi = 0; bi < 4; ++bi) {
            float xv = xs[(bg * 4 + bi) * 16 + kg * 8 + kk];
            acc[bi].x += xv * wq.x; acc[bi].y += xv * wq.y;
            acc[bi].z += xv * wq.z; acc[bi].w += xv * wq.w;
        }
    }
    __syncthreads();
    int slot = (bg * 128 + jq) * 4;
    if (kg == 1) {
#pragma unroll
        for (int bi = 0; bi < 4; ++bi) sc[slot + bi] = acc[bi];
    }
    __syncthreads();
    if (kg == 0) {
        float4 lb = make_float4(0.f, 0.f, 0.f, 0.f);
        if (kc == 0) {
            float4 bv4 = reinterpret_cast<const float4*>(bv)[jb * 128 + jq];
            lb.x = 1024.f * bv4.x; lb.y = 1024.f * bv4.y;
            lb.z = 1024.f * bv4.z; lb.w = 1024.f * bv4.w;
        }
        float* base = &g_vsum4[kc & 3][0];
#pragma unroll
        for (int bi = 0; bi < 4; ++bi) {
            float4 o = sc[slot + bi];
            o.x += acc[bi].x + lb.x; o.y += acc[bi].y + lb.y;
            o.z += acc[bi].z + lb.z; o.w += acc[bi].w + lb.w;
            red_add_v4(base + (bg * 4 + bi) * HD + jb * 512 + 4 * jq, o);
        }
    }
}

// k3: zc += vsum @ fc_w (+ fc_b on jc==0).  fc_w is [HD x DD] row-major.
// grid 256 (j-chunks of 16), 512 threads; 32 KB tile; jg-half combine.
__global__ void k3_z(const float* __restrict__ fcw, const float* __restrict__ fcb) {
    __shared__ float4 sw[16 * 128];
    __shared__ float4 sc[256 * 4];
    float* vs = reinterpret_cast<float*>(sc);

    int t = threadIdx.x;
    int jc = blockIdx.x;
    int j0 = jc * 16;

    const float4* w4 = reinterpret_cast<const float4*>(fcw);
#pragma unroll
    for (int u = 0; u < 4; ++u) {
        int g = t + u * 512;
        int jj = g >> 7, iq = g & 127;
        sw[g] = w4[(size_t)(j0 + jj) * (DD / 4) + iq];
    }
    if (t < 128) {
        int b = t >> 4, jj = t & 15;
        int a = b * HD + j0 + jj;
        vs[t] = g_vsum4[0][a] + g_vsum4[1][a] + g_vsum4[2][a] + g_vsum4[3][a];
    }
    __syncthreads();

    int iq = t & 127, jg = (t >> 7) & 1, bg = t >> 8;
    float4 acc[4];
#pragma unroll
    for (int i = 0; i < 4; ++i) acc[i] = make_float4(0.f, 0.f, 0.f, 0.f);
#pragma unroll
    for (int jj = 0; jj < 8; ++jj) {
        float4 wq = sw[(jg * 8 + jj) * 128 + iq];
#pragma unroll
        for (int bi = 0; bi < 4; ++bi) {
            float vv = vs[(bg * 4 + bi) * 16 + jg * 8 + jj];
            acc[bi].x += vv * wq.x; acc[bi].y += vv * wq.y;
            acc[bi].z += vv * wq.z; acc[bi].w += vv * wq.w;
        }
    }
    __syncthreads();
    int slot = (bg * 128 + iq) * 4;
    if (jg == 1) {
#pragma unroll
        for (int bi = 0; bi < 4; ++bi) sc[slot + bi] = acc[bi];
    }
    __syncthreads();
    if (jg == 0) {
        float4 fb = make_float4(0.f, 0.f, 0.f, 0.f);
        if (jc == 0) fb = reinterpret_cast<const float4*>(fcb)[iq];
        float* base = &g_zc[jc & 7][0];
#pragma unroll
        for (int bi = 0; bi < 4; ++bi) {
            float4 o = sc[slot + bi];
            o.x += acc[bi].x + fb.x; o.y += acc[bi].y + fb.y;
            o.z += acc[bi].z + fb.z; o.w += acc[bi].w + fb.w;
            red_add_v4(base + (bg * 4 + bi) * DD + 4 * iq, o);
        }
    }
}

// k4: out = LayerNorm(merge(zc)[b] + x[b,l]) * g + beta.
// 512 blocks x 256 threads, two rows per warp. The 8 x LDG.128 are issued
// FIRST so their latency overlaps the zc/ln staging + barrier (the staging
// chain was the serial critical path at 3.46 blocks/SM).
__global__ __launch_bounds__(256, 4) void k4_ln(
        const float* __restrict__ x,
        const float* __restrict__ lng, const float* __restrict__ lnb,
        float* __restrict__ out) {
    __shared__ float4 zs[128];   // merged z row for this b
    __shared__ float4 gs[128];   // ln_g
    __shared__ float4 bs[128];   // ln_b
    int t = threadIdx.x, blk = blockIdx.x;
    int b = blk >> 6;                      // 64 blocks (16 rows each) per batch

    int warp = t >> 5, lane = t & 31;
    int row0 = blk * 16 + warp * 2;
    const float4* xp0 = reinterpret_cast<const float4*>(x) + (size_t)row0 * 128;
    const float4* xp1 = xp0 + 128;

    // Issue x loads FIRST (independent of staging; overlap the barrier).
    float4 xa[4], xb[4];
#pragma unroll
    for (int i = 0; i < 4; ++i) xa[i] = xp0[lane + 32 * i];
#pragma unroll
    for (int i = 0; i < 4; ++i) xb[i] = xp1[lane + 32 * i];

    // Staging: warps 0-3 merge zc; warps 4-7 fetch ln params.
    if (t < 128) {
        float4 s = make_float4(0.f, 0.f, 0.f, 0.f);
#pragma unroll
        for (int c = 0; c < 8; ++c) {
            float4 v = reinterpret_cast<const float4*>(&g_zc[c][0])[b * 128 + t];
            s.x += v.x; s.y += v.y; s.z += v.z; s.w += v.w;
        }
        zs[t] = s;
    } else {
        int u = t - 128;
        gs[u] = reinterpret_cast<const float4*>(lng)[u];
        bs[u] = reinterpret_cast<const float4*>(lnb)[u];
    }
    __syncthreads();

    float sa = 0.f, qa = 0.f, sb = 0.f, qb = 0.f;
#pragma unroll
    for (int i = 0; i < 4; ++i) {
        float4 z = zs[lane + 32 * i];
        float y;
        y = xa[i].x + z.x; sa += y; qa += y * y;
        y = xa[i].y + z.y; sa += y; qa += y * y;
        y = xa[i].z + z.z; sa += y; qa += y * y;
        y = xa[i].w + z.w; sa += y; qa += y * y;
        y = xb[i].x + z.x; sb += y; qb += y * y;
        y = xb[i].y + z.y; sb += y; qb += y * y;
        y = xb[i].z + z.z; sb += y; qb += y * y;
        y = xb[i].w + z.w; sb += y; qb += y * y;
    }
#pragma unroll
    for (int o = 16; o > 0; o >>= 1) {
        sa += __shfl_xor_sync(0xFFFFFFFFu, sa, o);
        qa += __shfl_xor_sync(0xFFFFFFFFu, qa, o);
        sb += __shfl_xor_sync(0xFFFFFFFFu, sb, o);
        qb += __shfl_xor_sync(0xFFFFFFFFu, qb, o);
    }
    float mua  = sa * (1.0f / DD);
    float inva = rsqrtf(qa * (1.0f / DD) - mua * mua + 1e-5f);
    float mub  = sb * (1.0f / DD);
    float invb = rsqrtf(qb * (1.0f / DD) - mub * mub + 1e-5f);

    float4* op0 = reinterpret_cast<float4*>(out) + (size_t)row0 * 128;
    float4* op1 = op0 + 128;
#pragma unroll
    for (int i = 0; i < 4; ++i) {
        float4 z  = zs[lane + 32 * i];
        float4 gv = gs[lane + 32 * i];
        float4 be = bs[lane + 32 * i];
        float4 o;
        o.x = (xa[i].x + z.x - mua) * inva * gv.x + be.x;
        o.y = (xa[i].y + z.y - mua) * inva * gv.y + be.y;
        o.z = (xa[i].z + z.z - mua) * inva * gv.z + be.z;
        o.w = (xa[i].w + z.w - mua) * inva * gv.w + be.w;
        op0[lane + 32 * i] = o;
        o.x = (xb[i].x + z.x - mub) * invb * gv.x + be.x;
        o.y = (xb[i].y + z.y - mub) * invb * gv.y + be.y;
        o.z = (xb[i].z + z.z - mub) * invb * gv.z + be.z;
        o.w = (xb[i].w + z.w - mub) * invb * gv.w + be.w;
        op1[lane + 32 * i] = o;
    }

    // Epilogue resets for next replay (k4 reads neither buffer).
    float4 z4 = make_float4(0.f, 0.f, 0.f, 0.f);
    if (t < 64)
        reinterpret_cast<float4*>(&g_vsum4[0][0])[blk * 64 + t] = z4;   // 32768 quads
    if (t < 4)
        reinterpret_cast<float4*>(&g_xsum2[0][0])[blk * 4 + t] = z4;    // 2048 quads
}

extern "C" void kernel_launch(void* const* d_in, const int* in_sizes, int n_in,
                              void* d_out, int out_size) {
    const float* input = (const float*)d_in[0];
    const float* wv    = (const float*)d_in[5];
    const float* bv    = (const float*)d_in[6];
    const float* fcw   = (const float*)d_in[9];
    const float* fcb   = (const float*)d_in[10];
    const float* lng   = (const float*)d_in[11];
    const float* lnb   = (const float*)d_in[12];
    float* out = (float*)d_out;

    kA     <<<544, 256>>>(input);
    k2_vsum<<<dim3(8, 32), 512>>>(wv, bv);
    k3_z   <<<256, 512>>>(fcw, fcb);
    k4_ln  <<<512, 256>>>(input, lng, lnb, out);
}

// round 12
// speedup vs baseline: 1.2250x; 1.0933x over previous
#include <cuda_runtime.h>

#define BB 8
#define LL 1024
#define DD 512
#define HD 4096

// Accumulators. Zero at module load (first call OK); k4's epilogue re-zeroes
// xsum2/vsum4 for the next replay; zc re-zeroed by kA's extra blocks each call.
__device__ __align__(16) float g_xsum2[2][BB * DD];   // 32 KB
__device__ __align__(16) float g_vsum4[4][BB * HD];   // 512 KB
__device__ __align__(16) float g_zc[8][BB * DD];      // 128 KB

__device__ __forceinline__ void red_add_v4(float* a, float4 v) {
    asm volatile("red.global.add.v4.f32 [%0], {%1,%2,%3,%4};"
                 :: "l"(a), "f"(v.x), "f"(v.y), "f"(v.z), "f"(v.w) : "memory");
}

// kA: blocks [0,512): xsum += input over 16-row chunks (red into 2 copies).
//     blocks [512,544): zero g_zc for this call.
__global__ __launch_bounds__(256) void kA(const float* __restrict__ x) {
    cudaTriggerProgrammaticLaunchCompletion();   // let k2 start its prologue
    int blk = blockIdx.x, t = threadIdx.x;
    if (blk >= 512) {
        int q = (blk - 512) * 256 + t;   // 8192 quads
        reinterpret_cast<float4*>(&g_zc[0][0])[q] = make_float4(0.f, 0.f, 0.f, 0.f);
        return;
    }
    int b = blk >> 6, c = blk & 63;          // 64 L-chunks of 16 rows
    int h = t >> 7, q = t & 127;             // 8-row half, quad
    const float4* p = reinterpret_cast<const float4*>(x)
                    + (size_t)b * LL * 128 + (size_t)(c * 16 + h * 8) * 128 + q;
    float4 s = make_float4(0.f, 0.f, 0.f, 0.f);
#pragma unroll
    for (int r = 0; r < 8; ++r) {
        float4 v = p[r * 128];
        s.x += v.x; s.y += v.y; s.z += v.z; s.w += v.w;
    }
    red_add_v4(&g_xsum2[h][b * DD + 4 * q], s);
}

// k2: vsum += xsum @ wv (+ L*bv on kc==0).  wv is [DD x HD] row-major.
// PDL: weight staging overlaps kA; gridDependencySynchronize before xsum read.
__global__ void k2_vsum(const float* __restrict__ wv, const float* __restrict__ bv) {
    cudaTriggerProgrammaticLaunchCompletion();   // let k3 start its prologue
    __shared__ float4 sw[16 * 128];   // 32 KB
    __shared__ float4 sc[256 * 4];    // 16 KB; first 512 B doubles as xs
    float* xs = reinterpret_cast<float*>(sc);

    int t = threadIdx.x;
    int jb = blockIdx.x, kc = blockIdx.y;
    int k0 = kc * 16;

    // Independent prologue: stream the weight tile (runs under kA).
    const float4* w4 = reinterpret_cast<const float4*>(wv);
#pragma unroll
    for (int u = 0; u < 4; ++u) {
        int g = t + u * 512;
        int kk = g >> 7, jq = g & 127;
        sw[g] = w4[(size_t)(k0 + kk) * (HD / 4) + jb * 128 + jq];
    }

    cudaGridDependencySynchronize();             // kA's reds now visible

    if (t < 128) {
        int b = t >> 4, kk = t & 15;
        int a = b * DD + k0 + kk;
        xs[t] = g_xsum2[0][a] + g_xsum2[1][a];
    }
    __syncthreads();

    int jq = t & 127, kg = (t >> 7) & 1, bg = t >> 8;
    float4 acc[4];
#pragma unroll
    for (int i = 0; i < 4; ++i) acc[i] = make_float4(0.f, 0.f, 0.f, 0.f);
#pragma unroll
    for (int kk = 0; kk < 8; ++kk) {
        float4 wq = sw[(kg * 8 + kk) * 128 + jq];
#pragma unroll
        for (int bi = 0; bi < 4; ++bi) {
            float xv = xs[(bg * 4 + bi) * 16 + kg * 8 + kk];
            acc[bi].x += xv * wq.x; acc[bi].y += xv * wq.y;
            acc[bi].z += xv * wq.z; acc[bi].w += xv * wq.w;
        }
    }
    __syncthreads();
    int slot = (bg * 128 + jq) * 4;
    if (kg == 1) {
#pragma unroll
        for (int bi = 0; bi < 4; ++bi) sc[slot + bi] = acc[bi];
    }
    __syncthreads();
    if (kg == 0) {
        float4 lb = make_float4(0.f, 0.f, 0.f, 0.f);
        if (kc == 0) {
            float4 bv4 = reinterpret_cast<const float4*>(bv)[jb * 128 + jq];
            lb.x = 1024.f * bv4.x; lb.y = 1024.f * bv4.y;
            lb.z = 1024.f * bv4.z; lb.w = 1024.f * bv4.w;
        }
        float* base = &g_vsum4[kc & 3][0];
#pragma unroll
        for (int bi = 0; bi < 4; ++bi) {
            float4 o = sc[slot + bi];
            o.x += acc[bi].x + lb.x; o.y += acc[bi].y + lb.y;
            o.z += acc[bi].z + lb.z; o.w += acc[bi].w + lb.w;
            red_add_v4(base + (bg * 4 + bi) * HD + jb * 512 + 4 * jq, o);
        }
    }
}

// k3: zc += vsum @ fc_w (+ fc_b on jc==0).  fc_w is [HD x DD] row-major.
// PDL: weight staging overlaps k2; sync before vsum read.
__global__ void k3_z(const float* __restrict__ fcw, const float* __restrict__ fcb) {
    cudaTriggerProgrammaticLaunchCompletion();   // let k4 start its prologue
    __shared__ float4 sw[16 * 128];
    __shared__ float4 sc[256 * 4];
    float* vs = reinterpret_cast<float*>(sc);

    int t = threadIdx.x;
    int jc = blockIdx.x;
    int j0 = jc * 16;

    const float4* w4 = reinterpret_cast<const float4*>(fcw);
#pragma unroll
    for (int u = 0; u < 4; ++u) {
        int g = t + u * 512;
        int jj = g >> 7, iq = g & 127;
        sw[g] = w4[(size_t)(j0 + jj) * (DD / 4) + iq];
    }

    cudaGridDependencySynchronize();             // k2's reds now visible

    if (t < 128) {
        int b = t >> 4, jj = t & 15;
        int a = b * HD + j0 + jj;
        vs[t] = g_vsum4[0][a] + g_vsum4[1][a] + g_vsum4[2][a] + g_vsum4[3][a];
    }
    __syncthreads();

    int iq = t & 127, jg = (t >> 7) & 1, bg = t >> 8;
    float4 acc[4];
#pragma unroll
    for (int i = 0; i < 4; ++i) acc[i] = make_float4(0.f, 0.f, 0.f, 0.f);
#pragma unroll
    for (int jj = 0; jj < 8; ++jj) {
        float4 wq = sw[(jg * 8 + jj) * 128 + iq];
#pragma unroll
        for (int bi = 0; bi < 4; ++bi) {
            float vv = vs[(bg * 4 + bi) * 16 + jg * 8 + jj];
            acc[bi].x += vv * wq.x; acc[bi].y += vv * wq.y;
            acc[bi].z += vv * wq.z; acc[bi].w += vv * wq.w;
        }
    }
    __syncthreads();
    int slot = (bg * 128 + iq) * 4;
    if (jg == 1) {
#pragma unroll
        for (int bi = 0; bi < 4; ++bi) sc[slot + bi] = acc[bi];
    }
    __syncthreads();
    if (jg == 0) {
        float4 fb = make_float4(0.f, 0.f, 0.f, 0.f);
        if (jc == 0) fb = reinterpret_cast<const float4*>(fcb)[iq];
        float* base = &g_zc[jc & 7][0];
#pragma unroll
        for (int bi = 0; bi < 4; ++bi) {
            float4 o = sc[slot + bi];
            o.x += acc[bi].x + fb.x; o.y += acc[bi].y + fb.y;
            o.z += acc[bi].z + fb.z; o.w += acc[bi].w + fb.w;
            red_add_v4(base + (bg * 4 + bi) * DD + 4 * iq, o);
        }
    }
}

// k4: out = LayerNorm(merge(zc)[b] + x[b,l]) * g + beta.
// PDL: x loads + ln staging overlap k3; sync before zc merge.
__global__ __launch_bounds__(256, 4) void k4_ln(
        const float* __restrict__ x,
        const float* __restrict__ lng, const float* __restrict__ lnb,
        float* __restrict__ out) {
    __shared__ float4 zs[128];   // merged z row for this b
    __shared__ float4 gs[128];   // ln_g
    __shared__ float4 bs[128];   // ln_b
    int t = threadIdx.x, blk = blockIdx.x;
    int b = blk >> 6;                      // 64 blocks (16 rows each) per batch

    int warp = t >> 5, lane = t & 31;
    int row0 = blk * 16 + warp * 2;
    const float4* xp0 = reinterpret_cast<const float4*>(x) + (size_t)row0 * 128;
    const float4* xp1 = xp0 + 128;

    // Independent prologue (overlaps k3): x loads + ln params.
    float4 xa[4], xb[4];
#pragma unroll
    for (int i = 0; i < 4; ++i) xa[i] = xp0[lane + 32 * i];
#pragma unroll
    for (int i = 0; i < 4; ++i) xb[i] = xp1[lane + 32 * i];
    if (t >= 128) {
        int u = t - 128;
        gs[u] = reinterpret_cast<const float4*>(lng)[u];
        bs[u] = reinterpret_cast<const float4*>(lnb)[u];
    }

    cudaGridDependencySynchronize();             // k3's reds now visible

    if (t < 128) {
        float4 s = make_float4(0.f, 0.f, 0.f, 0.f);
#pragma unroll
        for (int c = 0; c < 8; ++c) {
            float4 v = reinterpret_cast<const float4*>(&g_zc[c][0])[b * 128 + t];
            s.x += v.x; s.y += v.y; s.z += v.z; s.w += v.w;
        }
        zs[t] = s;
    }
    __syncthreads();

    float sa = 0.f, qa = 0.f, sb = 0.f, qb = 0.f;
#pragma unroll
    for (int i = 0; i < 4; ++i) {
        float4 z = zs[lane + 32 * i];
        float y;
        y = xa[i].x + z.x; sa += y; qa += y * y;
        y = xa[i].y + z.y; sa += y; qa += y * y;
        y = xa[i].z + z.z; sa += y; qa += y * y;
        y = xa[i].w + z.w; sa += y; qa += y * y;
        y = xb[i].x + z.x; sb += y; qb += y * y;
        y = xb[i].y + z.y; sb += y; qb += y * y;
        y = xb[i].z + z.z; sb += y; qb += y * y;
        y = xb[i].w + z.w; sb += y; qb += y * y;
    }
#pragma unroll
    for (int o = 16; o > 0; o >>= 1) {
        sa += __shfl_xor_sync(0xFFFFFFFFu, sa, o);
        qa += __shfl_xor_sync(0xFFFFFFFFu, qa, o);
        sb += __shfl_xor_sync(0xFFFFFFFFu, sb, o);
        qb += __shfl_xor_sync(0xFFFFFFFFu, qb, o);
    }
    float mua  = sa * (1.0f / DD);
    float inva = rsqrtf(qa * (1.0f / DD) - mua * mua + 1e-5f);
    float mub  = sb * (1.0f / DD);
    float invb = rsqrtf(qb * (1.0f / DD) - mub * mub + 1e-5f);

    float4* op0 = reinterpret_cast<float4*>(out) + (size_t)row0 * 128;
    float4* op1 = op0 + 128;
#pragma unroll
    for (int i = 0; i < 4; ++i) {
        float4 z  = zs[lane + 32 * i];
        float4 gv = gs[lane + 32 * i];
        float4 be = bs[lane + 32 * i];
        float4 o;
        o.x = (xa[i].x + z.x - mua) * inva * gv.x + be.x;
        o.y = (xa[i].y + z.y - mua) * inva * gv.y + be.y;
        o.z = (xa[i].z + z.z - mua) * inva * gv.z + be.z;
        o.w = (xa[i].w + z.w - mua) * inva * gv.w + be.w;
        op0[lane + 32 * i] = o;
        o.x = (xb[i].x + z.x - mub) * invb * gv.x + be.x;
        o.y = (xb[i].y + z.y - mub) * invb * gv.y + be.y;
        o.z = (xb[i].z + z.z - mub) * invb * gv.z + be.z;
        o.w = (xb[i].w + z.w - mub) * invb * gv.w + be.w;
        op1[lane + 32 * i] = o;
    }

    // Epilogue resets for next replay (k4 reads neither buffer; runs after
    // the dependency sync so k3 is fully done).
    float4 z4 = make_float4(0.f, 0.f, 0.f, 0.f);
    if (t < 64)
        reinterpret_cast<float4*>(&g_vsum4[0][0])[blk * 64 + t] = z4;   // 32768 quads
    if (t < 4)
        reinterpret_cast<float4*>(&g_xsum2[0][0])[blk * 4 + t] = z4;    // 2048 quads
}

extern "C" void kernel_launch(void* const* d_in, const int* in_sizes, int n_in,
                              void* d_out, int out_size) {
    const float* input = (const float*)d_in[0];
    const float* wv    = (const float*)d_in[5];
    const float* bv    = (const float*)d_in[6];
    const float* fcw   = (const float*)d_in[9];
    const float* fcb   = (const float*)d_in[10];
    const float* lng   = (const float*)d_in[11];
    const float* lnb   = (const float*)d_in[12];
    float* out = (float*)d_out;

    // kA: normal launch.
    kA<<<544, 256>>>(input);

    // k2/k3/k4: PDL launches (overlap prologue with predecessor).
    cudaLaunchAttribute attr[1];
    attr[0].id = cudaLaunchAttributeProgrammaticStreamSerialization;
    attr[0].val.programmaticStreamSerializationAllowed = 1;

    {
        cudaLaunchConfig_t cfg{};
        cfg.gridDim = dim3(8, 32); cfg.blockDim = dim3(512);
        cfg.attrs = attr; cfg.numAttrs = 1; cfg.stream = 0;
        cudaLaunchKernelEx(&cfg, k2_vsum, wv, bv);
    }
    {
        cudaLaunchConfig_t cfg{};
        cfg.gridDim = dim3(256); cfg.blockDim = dim3(512);
        cfg.attrs = attr; cfg.numAttrs = 1; cfg.stream = 0;
        cudaLaunchKernelEx(&cfg, k3_z, fcw, fcb);
    }
    {
        cudaLaunchConfig_t cfg{};
        cfg.gridDim = dim3(512); cfg.blockDim = dim3(256);
        cfg.attrs = attr; cfg.numAttrs = 1; cfg.stream = 0;
        cudaLaunchKernelEx(&cfg, k4_ln, input, lng, lnb, out);
    }
}

// round 13
// speedup vs baseline: 1.2416x; 1.0135x over previous
#include <cuda_runtime.h>

#define BB 8
#define LL 1024
#define DD 512
#define HD 4096

// Accumulators. Zero at module load (first call OK); k4's epilogue re-zeroes
// xsum2/vsum4 for the next replay; zc re-zeroed by kA's extra blocks each call.
__device__ __align__(16) float g_xsum2[2][BB * DD];   // 32 KB
__device__ __align__(16) float g_vsum4[4][BB * HD];   // 512 KB
__device__ __align__(16) float g_zc[4][BB * DD];      // 64 KB (4 copies now)
__device__ __align__(16) float g_z[BB * DD];          // merged z (k3b output)

__device__ __forceinline__ void red_add_v4(float* a, float4 v) {
    asm volatile("red.global.add.v4.f32 [%0], {%1,%2,%3,%4};"
                 :: "l"(a), "f"(v.x), "f"(v.y), "f"(v.z), "f"(v.w) : "memory");
}

// kA: blocks [0,512): xsum += input over 16-row chunks (red into 2 copies).
//     blocks [512,528): zero g_zc (4096 quads) for this call.
__global__ __launch_bounds__(256) void kA(const float* __restrict__ x) {
    cudaTriggerProgrammaticLaunchCompletion();
    int blk = blockIdx.x, t = threadIdx.x;
    if (blk >= 512) {
        int q = (blk - 512) * 256 + t;   // 4096 quads
        reinterpret_cast<float4*>(&g_zc[0][0])[q] = make_float4(0.f, 0.f, 0.f, 0.f);
        return;
    }
    int b = blk >> 6, c = blk & 63;          // 64 L-chunks of 16 rows
    int h = t >> 7, q = t & 127;             // 8-row half, quad
    const float4* p = reinterpret_cast<const float4*>(x)
                    + (size_t)b * LL * 128 + (size_t)(c * 16 + h * 8) * 128 + q;
    float4 s = make_float4(0.f, 0.f, 0.f, 0.f);
#pragma unroll
    for (int r = 0; r < 8; ++r) {
        float4 v = p[r * 128];
        s.x += v.x; s.y += v.y; s.z += v.z; s.w += v.w;
    }
    red_add_v4(&g_xsum2[h][b * DD + 4 * q], s);
}

// k2: vsum += xsum @ wv (+ L*bv on kc==0).  PDL: weight staging overlaps kA.
__global__ void k2_vsum(const float* __restrict__ wv, const float* __restrict__ bv) {
    cudaTriggerProgrammaticLaunchCompletion();
    __shared__ float4 sw[16 * 128];   // 32 KB
    __shared__ float4 sc[256 * 4];    // 16 KB; first 512 B doubles as xs
    float* xs = reinterpret_cast<float*>(sc);

    int t = threadIdx.x;
    int jb = blockIdx.x, kc = blockIdx.y;
    int k0 = kc * 16;

    const float4* w4 = reinterpret_cast<const float4*>(wv);
#pragma unroll
    for (int u = 0; u < 4; ++u) {
        int g = t + u * 512;
        int kk = g >> 7, jq = g & 127;
        sw[g] = w4[(size_t)(k0 + kk) * (HD / 4) + jb * 128 + jq];
    }

    cudaGridDependencySynchronize();

    if (t < 128) {
        int b = t >> 4, kk = t & 15;
        int a = b * DD + k0 + kk;
        xs[t] = g_xsum2[0][a] + g_xsum2[1][a];
    }
    __syncthreads();

    int jq = t & 127, kg = (t >> 7) & 1, bg = t >> 8;
    float4 acc[4];
#pragma unroll
    for (int i = 0; i < 4; ++i) acc[i] = make_float4(0.f, 0.f, 0.f, 0.f);
#pragma unroll
    for (int kk = 0; kk < 8; ++kk) {
        float4 wq = sw[(kg * 8 + kk) * 128 + jq];
#pragma unroll
        for (int bi = 0; bi < 4; ++bi) {
            float xv = xs[(bg * 4 + bi) * 16 + kg * 8 + kk];
            acc[bi].x += xv * wq.x; acc[bi].y += xv * wq.y;
            acc[bi].z += xv * wq.z; acc[bi].w += xv * wq.w;
        }
    }
    __syncthreads();
    int slot = (bg * 128 + jq) * 4;
    if (kg == 1) {
#pragma unroll
        for (int bi = 0; bi < 4; ++bi) sc[slot + bi] = acc[bi];
    }
    __syncthreads();
    if (kg == 0) {
        float4 lb = make_float4(0.f, 0.f, 0.f, 0.f);
        if (kc == 0) {
            float4 bv4 = reinterpret_cast<const float4*>(bv)[jb * 128 + jq];
            lb.x = 1024.f * bv4.x; lb.y = 1024.f * bv4.y;
            lb.z = 1024.f * bv4.z; lb.w = 1024.f * bv4.w;
        }
        float* base = &g_vsum4[kc & 3][0];
#pragma unroll
        for (int bi = 0; bi < 4; ++bi) {
            float4 o = sc[slot + bi];
            o.x += acc[bi].x + lb.x; o.y += acc[bi].y + lb.y;
            o.z += acc[bi].z + lb.z; o.w += acc[bi].w + lb.w;
            red_add_v4(base + (bg * 4 + bi) * HD + jb * 512 + 4 * jq, o);
        }
    }
}

// k3: zc += vsum @ fc_w (+ fc_b on jc==0).  4 zc copies (64 reds/address).
__global__ void k3_z(const float* __restrict__ fcw, const float* __restrict__ fcb) {
    cudaTriggerProgrammaticLaunchCompletion();
    __shared__ float4 sw[16 * 128];
    __shared__ float4 sc[256 * 4];
    float* vs = reinterpret_cast<float*>(sc);

    int t = threadIdx.x;
    int jc = blockIdx.x;
    int j0 = jc * 16;

    const float4* w4 = reinterpret_cast<const float4*>(fcw);
#pragma unroll
    for (int u = 0; u < 4; ++u) {
        int g = t + u * 512;
        int jj = g >> 7, iq = g & 127;
        sw[g] = w4[(size_t)(j0 + jj) * (DD / 4) + iq];
    }

    cudaGridDependencySynchronize();

    if (t < 128) {
        int b = t >> 4, jj = t & 15;
        int a = b * HD + j0 + jj;
        vs[t] = g_vsum4[0][a] + g_vsum4[1][a] + g_vsum4[2][a] + g_vsum4[3][a];
    }
    __syncthreads();

    int iq = t & 127, jg = (t >> 7) & 1, bg = t >> 8;
    float4 acc[4];
#pragma unroll
    for (int i = 0; i < 4; ++i) acc[i] = make_float4(0.f, 0.f, 0.f, 0.f);
#pragma unroll
    for (int jj = 0; jj < 8; ++jj) {
        float4 wq = sw[(jg * 8 + jj) * 128 + iq];
#pragma unroll
        for (int bi = 0; bi < 4; ++bi) {
            float vv = vs[(bg * 4 + bi) * 16 + jg * 8 + jj];
            acc[bi].x += vv * wq.x; acc[bi].y += vv * wq.y;
            acc[bi].z += vv * wq.z; acc[bi].w += vv * wq.w;
        }
    }
    __syncthreads();
    int slot = (bg * 128 + iq) * 4;
    if (jg == 1) {
#pragma unroll
        for (int bi = 0; bi < 4; ++bi) sc[slot + bi] = acc[bi];
    }
    __syncthreads();
    if (jg == 0) {
        float4 fb = make_float4(0.f, 0.f, 0.f, 0.f);
        if (jc == 0) fb = reinterpret_cast<const float4*>(fcb)[iq];
        float* base = &g_zc[jc & 3][0];
#pragma unroll
        for (int bi = 0; bi < 4; ++bi) {
            float4 o = sc[slot + bi];
            o.x += acc[bi].x + fb.x; o.y += acc[bi].y + fb.y;
            o.z += acc[bi].z + fb.z; o.w += acc[bi].w + fb.w;
            red_add_v4(base + (bg * 4 + bi) * DD + 4 * iq, o);
        }
    }
}

// k3b: merge zc[4] -> g_z. Tiny PDL link kernel — hidden under k4's prologue.
__global__ void k3b_merge() {
    cudaTriggerProgrammaticLaunchCompletion();   // let k4 launch its prologue
    cudaGridDependencySynchronize();             // k3's reds visible
    int q = blockIdx.x * 512 + threadIdx.x;      // 1024 quads / 2 blocks
    float4 s = make_float4(0.f, 0.f, 0.f, 0.f);
#pragma unroll
    for (int c = 0; c < 4; ++c) {
        float4 v = reinterpret_cast<const float4*>(&g_zc[c][0])[q];
        s.x += v.x; s.y += v.y; s.z += v.z; s.w += v.w;
    }
    reinterpret_cast<float4*>(g_z)[q] = s;
}

// k4: out = LayerNorm(g_z[b] + x[b,l]) * g + beta.
// PDL: x loads + ln staging overlap k3/k3b; post-sync z stage is ONE load.
__global__ __launch_bounds__(256, 4) void k4_ln(
        const float* __restrict__ x,
        const float* __restrict__ lng, const float* __restrict__ lnb,
        float* __restrict__ out) {
    __shared__ float4 zs[128];   // merged z row for this b
    __shared__ float4 gs[128];   // ln_g
    __shared__ float4 bs[128];   // ln_b
    int t = threadIdx.x, blk = blockIdx.x;
    int b = blk >> 6;                      // 64 blocks (16 rows each) per batch

    int warp = t >> 5, lane = t & 31;
    int row0 = blk * 16 + warp * 2;
    const float4* xp0 = reinterpret_cast<const float4*>(x) + (size_t)row0 * 128;
    const float4* xp1 = xp0 + 128;

    // Independent prologue (overlaps k3 + k3b): x loads + ln params.
    float4 xa[4], xb[4];
#pragma unroll
    for (int i = 0; i < 4; ++i) xa[i] = xp0[lane + 32 * i];
#pragma unroll
    for (int i = 0; i < 4; ++i) xb[i] = xp1[lane + 32 * i];
    if (t >= 128) {
        int u = t - 128;
        gs[u] = reinterpret_cast<const float4*>(lng)[u];
        bs[u] = reinterpret_cast<const float4*>(lnb)[u];
    }

    cudaGridDependencySynchronize();             // k3b's g_z visible

    if (t < 128)
        zs[t] = reinterpret_cast<const float4*>(g_z)[b * 128 + t];
    __syncthreads();

    float sa = 0.f, qa = 0.f, sb = 0.f, qb = 0.f;
#pragma unroll
    for (int i = 0; i < 4; ++i) {
        float4 z = zs[lane + 32 * i];
        float y;
        y = xa[i].x + z.x; sa += y; qa += y * y;
        y = xa[i].y + z.y; sa += y; qa += y * y;
        y = xa[i].z + z.z; sa += y; qa += y * y;
        y = xa[i].w + z.w; sa += y; qa += y * y;
        y = xb[i].x + z.x; sb += y; qb += y * y;
        y = xb[i].y + z.y; sb += y; qb += y * y;
        y = xb[i].z + z.z; sb += y; qb += y * y;
        y = xb[i].w + z.w; sb += y; qb += y * y;
    }
#pragma unroll
    for (int o = 16; o > 0; o >>= 1) {
        sa += __shfl_xor_sync(0xFFFFFFFFu, sa, o);
        qa += __shfl_xor_sync(0xFFFFFFFFu, qa, o);
        sb += __shfl_xor_sync(0xFFFFFFFFu, sb, o);
        qb += __shfl_xor_sync(0xFFFFFFFFu, qb, o);
    }
    float mua  = sa * (1.0f / DD);
    float inva = rsqrtf(qa * (1.0f / DD) - mua * mua + 1e-5f);
    float mub  = sb * (1.0f / DD);
    float invb = rsqrtf(qb * (1.0f / DD) - mub * mub + 1e-5f);

    float4* op0 = reinterpret_cast<float4*>(out) + (size_t)row0 * 128;
    float4* op1 = op0 + 128;
#pragma unroll
    for (int i = 0; i < 4; ++i) {
        float4 z  = zs[lane + 32 * i];
        float4 gv = gs[lane + 32 * i];
        float4 be = bs[lane + 32 * i];
        float4 o;
        o.x = (xa[i].x + z.x - mua) * inva * gv.x + be.x;
        o.y = (xa[i].y + z.y - mua) * inva * gv.y + be.y;
        o.z = (xa[i].z + z.z - mua) * inva * gv.z + be.z;
        o.w = (xa[i].w + z.w - mua) * inva * gv.w + be.w;
        op0[lane + 32 * i] = o;
        o.x = (xb[i].x + z.x - mub) * invb * gv.x + be.x;
        o.y = (xb[i].y + z.y - mub) * invb * gv.y + be.y;
        o.z = (xb[i].z + z.z - mub) * invb * gv.z + be.z;
        o.w = (xb[i].w + z.w - mub) * invb * gv.w + be.w;
        op1[lane + 32 * i] = o;
    }

    // Epilogue resets for next replay (k4 reads neither buffer).
    float4 z4 = make_float4(0.f, 0.f, 0.f, 0.f);
    if (t < 64)
        reinterpret_cast<float4*>(&g_vsum4[0][0])[blk * 64 + t] = z4;   // 32768 quads
    if (t < 4)
        reinterpret_cast<float4*>(&g_xsum2[0][0])[blk * 4 + t] = z4;    // 2048 quads
}

extern "C" void kernel_launch(void* const* d_in, const int* in_sizes, int n_in,
                              void* d_out, int out_size) {
    const float* input = (const float*)d_in[0];
    const float* wv    = (const float*)d_in[5];
    const float* bv    = (const float*)d_in[6];
    const float* fcw   = (const float*)d_in[9];
    const float* fcb   = (const float*)d_in[10];
    const float* lng   = (const float*)d_in[11];
    const float* lnb   = (const float*)d_in[12];
    float* out = (float*)d_out;

    kA<<<528, 256>>>(input);

    cudaLaunchAttribute attr[1];
    attr[0].id = cudaLaunchAttributeProgrammaticStreamSerialization;
    attr[0].val.programmaticStreamSerializationAllowed = 1;

    {
        cudaLaunchConfig_t cfg{};
        cfg.gridDim = dim3(8, 32); cfg.blockDim = dim3(512);
        cfg.attrs = attr; cfg.numAttrs = 1; cfg.stream = 0;
        cudaLaunchKernelEx(&cfg, k2_vsum, wv, bv);
    }
    {
        cudaLaunchConfig_t cfg{};
        cfg.gridDim = dim3(256); cfg.blockDim = dim3(512);
        cfg.attrs = attr; cfg.numAttrs = 1; cfg.stream = 0;
        cudaLaunchKernelEx(&cfg, k3_z, fcw, fcb);
    }
    {
        cudaLaunchConfig_t cfg{};
        cfg.gridDim = dim3(2); cfg.blockDim = dim3(512);
        cfg.attrs = attr; cfg.numAttrs = 1; cfg.stream = 0;
        cudaLaunchKernelEx(&cfg, k3b_merge);
    }
    {
        cudaLaunchConfig_t cfg{};
        cfg.gridDim = dim3(512); cfg.blockDim = dim3(256);
        cfg.attrs = attr; cfg.numAttrs = 1; cfg.stream = 0;
        cudaLaunchKernelEx(&cfg, k4_ln, input, lng, lnb, out);
    }
}